// round 8
// baseline (speedup 1.0000x reference)
#include <cuda_runtime.h>
#include <math.h>
#include <stdint.h>

#define D_MODEL 768
#define N_HEADS 12
#define HEAD_DIM 64
#define SEQ 2048
#define BATCH 2
#define QKV_N (3 * D_MODEL)
#define M_TOK (BATCH * SEQ)
#define SCALE 0.125f

// Scratch (allocation-free rule: __device__ globals)
__device__ float g_qkv[(size_t)M_TOK * QKV_N];    // [B*S, 3*D] (Q | K | V)
__device__ float g_attn[(size_t)M_TOK * D_MODEL]; // [B*S, D] attention output

__device__ __forceinline__ uint32_t f2tf32(float x) {
    uint32_t r;
    asm("cvt.rna.tf32.f32 %0, %1;" : "=r"(r) : "f"(x));
    return r;
}

__device__ __forceinline__ void mma_tf32(float* c, const uint32_t* a, const uint32_t* b) {
    asm volatile("mma.sync.aligned.m16n8k8.row.col.f32.tf32.tf32.f32 "
                 "{%0,%1,%2,%3}, {%4,%5,%6,%7}, {%8,%9}, {%0,%1,%2,%3};"
                 : "+f"(c[0]), "+f"(c[1]), "+f"(c[2]), "+f"(c[3])
                 : "r"(a[0]), "r"(a[1]), "r"(a[2]), "r"(a[3]),
                   "r"(b[0]), "r"(b[1]));
}

// ---------------------------------------------------------------------------
// tf32 tensor-core GEMM: 128x128x32 block tile, 512 threads = 16 warps in a
// 4(M)x4(N) grid, warp tile 32x32 (2 m-frags x 4 n-frags). Double-buffered.
// ---------------------------------------------------------------------------
#define AS_STRIDE 36
#define BS_STRIDE 132
#define AS_TILE (128 * AS_STRIDE)
#define BS_TILE (32 * BS_STRIDE)
#define GEMM_SMEM ((2 * AS_TILE + 2 * BS_TILE) * 4)

__global__ __launch_bounds__(512) void gemm_tf32(const float* __restrict__ A,
                                                 const float* __restrict__ B,
                                                 const float* __restrict__ bias,
                                                 float* __restrict__ C,
                                                 int M, int N, int K)
{
    extern __shared__ uint32_t smu[];
    uint32_t* As = smu;
    uint32_t* Bs = smu + 2 * AS_TILE;

    const int tid  = threadIdx.x;
    const int lane = tid & 31;
    const int wid  = tid >> 5;
    const int wm   = (wid & 3) * 32;
    const int wn   = (wid >> 2) * 32;
    const int row0 = blockIdx.y * 128;
    const int col0 = blockIdx.x * 128;
    const int gid  = lane >> 2;
    const int tig  = lane & 3;

    float4 pa[2], pb[2];

    #pragma unroll
    for (int i = 0; i < 2; i++) {
        const int idx = tid + i * 512;
        pa[i] = *(const float4*)&A[(size_t)(row0 + (idx >> 3)) * K + (idx & 7) * 4];
        pb[i] = *(const float4*)&B[(size_t)(idx >> 5) * N + col0 + (idx & 31) * 4];
    }
    #pragma unroll
    for (int i = 0; i < 2; i++) {
        const int idx = tid + i * 512;
        uint32_t* p = As + (idx >> 3) * AS_STRIDE + (idx & 7) * 4;
        p[0] = f2tf32(pa[i].x); p[1] = f2tf32(pa[i].y);
        p[2] = f2tf32(pa[i].z); p[3] = f2tf32(pa[i].w);
        uint32_t* q = Bs + (idx >> 5) * BS_STRIDE + (idx & 31) * 4;
        q[0] = f2tf32(pb[i].x); q[1] = f2tf32(pb[i].y);
        q[2] = f2tf32(pb[i].z); q[3] = f2tf32(pb[i].w);
    }
    __syncthreads();

    float c[2][4][4] = {};
    const int nkt = K >> 5;
    int buf = 0;

    for (int t = 0; t < nkt; t++) {
        if (t + 1 < nkt) {
            const int k0 = (t + 1) * 32;
            #pragma unroll
            for (int i = 0; i < 2; i++) {
                const int idx = tid + i * 512;
                pa[i] = *(const float4*)&A[(size_t)(row0 + (idx >> 3)) * K + k0 + (idx & 7) * 4];
                pb[i] = *(const float4*)&B[(size_t)(k0 + (idx >> 5)) * N + col0 + (idx & 31) * 4];
            }
        }

        #pragma unroll
        for (int ks = 0; ks < 4; ks++) {
            uint32_t af[2][4], bf[4][2];
            const uint32_t* Ab = As + buf * AS_TILE + (wm + gid) * AS_STRIDE + ks * 8 + tig;
            #pragma unroll
            for (int mt = 0; mt < 2; mt++) {
                const uint32_t* p = Ab + mt * 16 * AS_STRIDE;
                af[mt][0] = p[0];
                af[mt][1] = p[8 * AS_STRIDE];
                af[mt][2] = p[4];
                af[mt][3] = p[8 * AS_STRIDE + 4];
            }
            const uint32_t* Bb = Bs + buf * BS_TILE + (ks * 8 + tig) * BS_STRIDE + wn + gid;
            #pragma unroll
            for (int nt = 0; nt < 4; nt++) {
                const uint32_t* p = Bb + nt * 8;
                bf[nt][0] = p[0];
                bf[nt][1] = p[4 * BS_STRIDE];
            }
            #pragma unroll
            for (int mt = 0; mt < 2; mt++)
                #pragma unroll
                for (int nt = 0; nt < 4; nt++)
                    mma_tf32(c[mt][nt], af[mt], bf[nt]);
        }

        if (t + 1 < nkt) {
            buf ^= 1;
            #pragma unroll
            for (int i = 0; i < 2; i++) {
                const int idx = tid + i * 512;
                uint32_t* p = As + buf * AS_TILE + (idx >> 3) * AS_STRIDE + (idx & 7) * 4;
                p[0] = f2tf32(pa[i].x); p[1] = f2tf32(pa[i].y);
                p[2] = f2tf32(pa[i].z); p[3] = f2tf32(pa[i].w);
                uint32_t* q = Bs + buf * BS_TILE + (idx >> 5) * BS_STRIDE + (idx & 31) * 4;
                q[0] = f2tf32(pb[i].x); q[1] = f2tf32(pb[i].y);
                q[2] = f2tf32(pb[i].z); q[3] = f2tf32(pb[i].w);
            }
            __syncthreads();
        }
    }

    #pragma unroll
    for (int nt = 0; nt < 4; nt++) {
        const int cc = col0 + wn + nt * 8 + 2 * tig;
        const float b0 = bias ? bias[cc]     : 0.f;
        const float b1 = bias ? bias[cc + 1] : 0.f;
        #pragma unroll
        for (int mt = 0; mt < 2; mt++) {
            const int r = row0 + wm + mt * 16 + gid;
            float2 v0 = make_float2(c[mt][nt][0] + b0, c[mt][nt][1] + b1);
            float2 v1 = make_float2(c[mt][nt][2] + b0, c[mt][nt][3] + b1);
            *(float2*)&C[(size_t)r * N + cc]       = v0;
            *(float2*)&C[(size_t)(r + 8) * N + cc] = v1;
        }
    }
}

// ---------------------------------------------------------------------------
// Tensor-core causal flash attention. 512 threads = 16 warps.
// Q tile = 128 rows, K/V tile = 64 rows. Warp grid 8(M)x2(N): warp tile 16x32.
// S = (Q*SCALE)K^T via tf32 mma -> smem; fp32 online softmax (16x32 thread
// layout, 4 rows/thread); P in place as tf32; O += P V via tf32 mma with O
// fragments register-resident across kt. 128-row tiles halve per-work K/V
// reload + sync overhead vs 64-row tiles.
// ---------------------------------------------------------------------------
#define FSTR 68
#define FLASH_SMEM ((128 * FSTR + 64 * FSTR + 64 * FSTR + 128 * FSTR) * 4 + 256 * 4)

__global__ __launch_bounds__(512) void flash_mma(const float* __restrict__ qkv,
                                                 float* __restrict__ out)
{
    extern __shared__ uint32_t smu[];
    uint32_t* Qt = smu;                      // [128][FSTR] tf32 row-major
    uint32_t* Kt = Qt + 128 * FSTR;          // [64][FSTR]  tf32 row-major (col-major B)
    uint32_t* Vt = Kt + 64 * FSTR;           // [64->d][FSTR] V transposed (col-major B)
    float*    Ss = (float*)(Vt + 64 * FSTR); // [128][FSTR] scores -> P (tf32) in place
    float*    alpha_s = (float*)(Ss + 128 * FSTR);  // [128]
    float*    linv_s  = alpha_s + 128;              // [128]

    const int tid  = threadIdx.x;
    const int lane = tid & 31;
    const int wid  = tid >> 5;
    const int wm   = (wid & 7) * 16;    // 8 warps along M (128 rows)
    const int wn   = (wid >> 3) * 32;   // 2 warps along N (64 cols)
    const int gid  = lane >> 2;
    const int tig  = lane & 3;
    const int tx   = tid & 15;          // softmax col group
    const int ty   = tid >> 4;          // softmax row group (0..31)
    const int qt   = gridDim.x - 1 - blockIdx.x;  // heavy blocks first
    const int h    = blockIdx.y;
    const int b    = blockIdx.z;

    // --- load Q tile (128 rows): scaled, tf32, row-major ---
    {
        const float* qbase = qkv + ((size_t)(b * SEQ + qt * 128)) * QKV_N + h * HEAD_DIM;
        const int r   = tid & 127;
        const int cg0 = tid >> 7;       // 0..3
        #pragma unroll
        for (int it = 0; it < 4; it++) {
            const int d4 = (cg0 + it * 4) * 4;
            float4 v = *(const float4*)(qbase + (size_t)r * QKV_N + d4);
            uint4 u;
            u.x = f2tf32(v.x * SCALE); u.y = f2tf32(v.y * SCALE);
            u.z = f2tf32(v.z * SCALE); u.w = f2tf32(v.w * SCALE);
            *(uint4*)&Qt[r * FSTR + d4] = u;
        }
    }

    float co[4][4] = {};   // O fragments
    float m[4], l[4];
    #pragma unroll
    for (int i = 0; i < 4; i++) { m[i] = -1e30f; l[i] = 0.f; }

    const int ktmax = 2 * qt + 1;
    for (int kt = 0; kt <= ktmax; kt++) {
        __syncthreads();  // previous tile fully consumed
        {
            const float* kb = qkv + ((size_t)(b * SEQ + kt * 64)) * QKV_N + D_MODEL + h * HEAD_DIM;
            const float* vb = kb + D_MODEL;
            const int r   = tid & 63;
            const int cg0 = tid >> 6;   // 0..7
            #pragma unroll
            for (int it = 0; it < 2; it++) {
                const int d4 = (cg0 + it * 8) * 4;
                float4 kv = *(const float4*)(kb + (size_t)r * QKV_N + d4);
                uint4 u;
                u.x = f2tf32(kv.x); u.y = f2tf32(kv.y);
                u.z = f2tf32(kv.z); u.w = f2tf32(kv.w);
                *(uint4*)&Kt[r * FSTR + d4] = u;
                float4 vv = *(const float4*)(vb + (size_t)r * QKV_N + d4);
                Vt[(d4 + 0) * FSTR + r] = f2tf32(vv.x);
                Vt[(d4 + 1) * FSTR + r] = f2tf32(vv.y);
                Vt[(d4 + 2) * FSTR + r] = f2tf32(vv.z);
                Vt[(d4 + 3) * FSTR + r] = f2tf32(vv.w);
            }
        }
        __syncthreads();

        // --- S = Q K^T (tf32 mma) ---
        float cs[4][4] = {};
        #pragma unroll
        for (int ks = 0; ks < 8; ks++) {
            uint32_t af[4], bf[4][2];
            const uint32_t* Ap = Qt + (wm + gid) * FSTR + ks * 8 + tig;
            af[0] = Ap[0];
            af[1] = Ap[8 * FSTR];
            af[2] = Ap[4];
            af[3] = Ap[8 * FSTR + 4];
            #pragma unroll
            for (int nt = 0; nt < 4; nt++) {
                const uint32_t* Bp = Kt + (wn + nt * 8 + gid) * FSTR + ks * 8 + tig;
                bf[nt][0] = Bp[0];
                bf[nt][1] = Bp[4];
            }
            #pragma unroll
            for (int nt = 0; nt < 4; nt++)
                mma_tf32(cs[nt], af, bf[nt]);
        }
        #pragma unroll
        for (int nt = 0; nt < 4; nt++) {
            const int cc = wn + nt * 8 + 2 * tig;
            *(float2*)&Ss[(wm + gid) * FSTR + cc]     = make_float2(cs[nt][0], cs[nt][1]);
            *(float2*)&Ss[(wm + gid + 8) * FSTR + cc] = make_float2(cs[nt][2], cs[nt][3]);
        }
        __syncthreads();

        // --- fp32 online softmax; P written in place as tf32 ---
        const int jbase = (kt - 2 * qt) * 64;  // mask threshold offset (only last 2 tiles)
        #pragma unroll
        for (int rr = 0; rr < 4; rr++) {
            const int row = ty * 4 + rr;
            float4 s4 = *(float4*)&Ss[row * FSTR + tx * 4];
            if (kt >= 2 * qt) {  // causal mask within the two diagonal tiles
                if (jbase + tx * 4 + 0 > row) s4.x = -1e30f;
                if (jbase + tx * 4 + 1 > row) s4.y = -1e30f;
                if (jbase + tx * 4 + 2 > row) s4.z = -1e30f;
                if (jbase + tx * 4 + 3 > row) s4.w = -1e30f;
            }
            float tm = fmaxf(fmaxf(s4.x, s4.y), fmaxf(s4.z, s4.w));
            tm = fmaxf(tm, __shfl_xor_sync(0xFFFFFFFFu, tm, 1));
            tm = fmaxf(tm, __shfl_xor_sync(0xFFFFFFFFu, tm, 2));
            tm = fmaxf(tm, __shfl_xor_sync(0xFFFFFFFFu, tm, 4));
            tm = fmaxf(tm, __shfl_xor_sync(0xFFFFFFFFu, tm, 8));
            const float mn = fmaxf(m[rr], tm);
            const float al = __expf(m[rr] - mn);
            m[rr] = mn;
            float p0 = __expf(s4.x - mn);
            float p1 = __expf(s4.y - mn);
            float p2 = __expf(s4.z - mn);
            float p3 = __expf(s4.w - mn);
            float rs = (p0 + p1) + (p2 + p3);
            rs += __shfl_xor_sync(0xFFFFFFFFu, rs, 1);
            rs += __shfl_xor_sync(0xFFFFFFFFu, rs, 2);
            rs += __shfl_xor_sync(0xFFFFFFFFu, rs, 4);
            rs += __shfl_xor_sync(0xFFFFFFFFu, rs, 8);
            l[rr] = l[rr] * al + rs;
            if (tx == 0) alpha_s[row] = al;
            uint4 u;
            u.x = f2tf32(p0); u.y = f2tf32(p1);
            u.z = f2tf32(p2); u.w = f2tf32(p3);
            *(uint4*)&Ss[row * FSTR + tx * 4] = u;  // P in place
        }
        __syncthreads();

        // --- rescale O fragments, then O += P V (tf32 mma) ---
        const float a_lo = alpha_s[wm + gid];
        const float a_hi = alpha_s[wm + gid + 8];
        #pragma unroll
        for (int nt = 0; nt < 4; nt++) {
            co[nt][0] *= a_lo; co[nt][1] *= a_lo;
            co[nt][2] *= a_hi; co[nt][3] *= a_hi;
        }
        const uint32_t* Ps = (const uint32_t*)Ss;
        #pragma unroll
        for (int ks = 0; ks < 8; ks++) {
            uint32_t af[4], bf[4][2];
            const uint32_t* Ap = Ps + (wm + gid) * FSTR + ks * 8 + tig;
            af[0] = Ap[0];
            af[1] = Ap[8 * FSTR];
            af[2] = Ap[4];
            af[3] = Ap[8 * FSTR + 4];
            #pragma unroll
            for (int nt = 0; nt < 4; nt++) {
                const uint32_t* Bp = Vt + (wn + nt * 8 + gid) * FSTR + ks * 8 + tig;
                bf[nt][0] = Bp[0];
                bf[nt][1] = Bp[4];
            }
            #pragma unroll
            for (int nt = 0; nt < 4; nt++)
                mma_tf32(co[nt], af, bf[nt]);
        }
    }

    // --- epilogue ---
    if (tx == 0) {
        #pragma unroll
        for (int rr = 0; rr < 4; rr++)
            linv_s[ty * 4 + rr] = 1.f / l[rr];
    }
    __syncthreads();
    const float inv_lo = linv_s[wm + gid];
    const float inv_hi = linv_s[wm + gid + 8];
    float* ob = out + ((size_t)(b * SEQ + qt * 128)) * D_MODEL + h * HEAD_DIM;
    #pragma unroll
    for (int nt = 0; nt < 4; nt++) {
        const int cc = wn + nt * 8 + 2 * tig;
        float2 v0 = make_float2(co[nt][0] * inv_lo, co[nt][1] * inv_lo);
        float2 v1 = make_float2(co[nt][2] * inv_hi, co[nt][3] * inv_hi);
        *(float2*)&ob[(size_t)(wm + gid) * D_MODEL + cc]     = v0;
        *(float2*)&ob[(size_t)(wm + gid + 8) * D_MODEL + cc] = v1;
    }
}

// ---------------------------------------------------------------------------
// Launch: tf32 QKV GEMM -> tf32 flash attention -> tf32 out projection (+bias)
// Inputs: x, attn_mask (ignored; causal known), W_qkv, W_proj, b_proj
// ---------------------------------------------------------------------------
extern "C" void kernel_launch(void* const* d_in, const int* in_sizes, int n_in,
                              void* d_out, int out_size)
{
    (void)in_sizes; (void)n_in; (void)out_size;
    const float* x      = (const float*)d_in[0];
    const float* W_qkv  = (const float*)d_in[2];
    const float* W_proj = (const float*)d_in[3];
    const float* b_proj = (const float*)d_in[4];
    float* out = (float*)d_out;

    float *qkv, *attn;
    cudaGetSymbolAddress((void**)&qkv,  g_qkv);
    cudaGetSymbolAddress((void**)&attn, g_attn);

    cudaFuncSetAttribute(gemm_tf32, cudaFuncAttributeMaxDynamicSharedMemorySize, GEMM_SMEM);
    cudaFuncSetAttribute(flash_mma, cudaFuncAttributeMaxDynamicSharedMemorySize, FLASH_SMEM);

    // 1) QKV projection: [4096,768] @ [768,2304]  (tf32 tensor cores)
    gemm_tf32<<<dim3(QKV_N / 128, M_TOK / 128), 512, GEMM_SMEM>>>(x, W_qkv, nullptr, qkv,
                                                                  M_TOK, QKV_N, D_MODEL);

    // 2) causal flash attention per (q-tile, head, batch)  (tf32 tensor cores)
    flash_mma<<<dim3(SEQ / 128, N_HEADS, BATCH), 512, FLASH_SMEM>>>(qkv, attn);

    // 3) output projection + bias: [4096,768] @ [768,768]  (tf32 tensor cores)
    gemm_tf32<<<dim3(D_MODEL / 128, M_TOK / 128), 512, GEMM_SMEM>>>(attn, W_proj, b_proj, out,
                                                                    M_TOK, D_MODEL, D_MODEL);
}

// round 9
// speedup vs baseline: 1.1003x; 1.1003x over previous
#include <cuda_runtime.h>
#include <math.h>
#include <stdint.h>

#define D_MODEL 768
#define N_HEADS 12
#define HEAD_DIM 64
#define SEQ 2048
#define BATCH 2
#define QKV_N (3 * D_MODEL)
#define M_TOK (BATCH * SEQ)
#define SCALE 0.125f

// Scratch (allocation-free rule: __device__ globals)
__device__ float g_qkv[(size_t)M_TOK * QKV_N];    // [B*S, 3*D] (Q | K | V)
__device__ float g_attn[(size_t)M_TOK * D_MODEL]; // [B*S, D] attention output

__device__ __forceinline__ uint32_t f2tf32(float x) {
    uint32_t r;
    asm("cvt.rna.tf32.f32 %0, %1;" : "=r"(r) : "f"(x));
    return r;
}

__device__ __forceinline__ void mma_tf32(float* c, const uint32_t* a, const uint32_t* b) {
    asm volatile("mma.sync.aligned.m16n8k8.row.col.f32.tf32.tf32.f32 "
                 "{%0,%1,%2,%3}, {%4,%5,%6,%7}, {%8,%9}, {%0,%1,%2,%3};"
                 : "+f"(c[0]), "+f"(c[1]), "+f"(c[2]), "+f"(c[3])
                 : "r"(a[0]), "r"(a[1]), "r"(a[2]), "r"(a[3]),
                   "r"(b[0]), "r"(b[1]));
}

// ---------------------------------------------------------------------------
// tf32 tensor-core GEMM (round-7 config: 256 threads, 8 warps 2Mx4N,
// warp tile 64x32, 128x128x32 block tile, double-buffered). Measured 151.9us.
// ---------------------------------------------------------------------------
#define AS_STRIDE 36
#define BS_STRIDE 132
#define AS_TILE (128 * AS_STRIDE)
#define BS_TILE (32 * BS_STRIDE)
#define GEMM_SMEM ((2 * AS_TILE + 2 * BS_TILE) * 4)

__global__ __launch_bounds__(256) void gemm_tf32(const float* __restrict__ A,
                                                 const float* __restrict__ B,
                                                 const float* __restrict__ bias,
                                                 float* __restrict__ C,
                                                 int M, int N, int K)
{
    extern __shared__ uint32_t smu[];
    uint32_t* As = smu;
    uint32_t* Bs = smu + 2 * AS_TILE;

    const int tid  = threadIdx.x;
    const int lane = tid & 31;
    const int wid  = tid >> 5;
    const int wm   = (wid & 1) * 64;
    const int wn   = (wid >> 1) * 32;
    const int row0 = blockIdx.y * 128;
    const int col0 = blockIdx.x * 128;
    const int gid  = lane >> 2;
    const int tig  = lane & 3;

    float4 pa[4], pb[4];

    #pragma unroll
    for (int i = 0; i < 4; i++) {
        const int idx = tid + i * 256;
        pa[i] = *(const float4*)&A[(size_t)(row0 + (idx >> 3)) * K + (idx & 7) * 4];
        pb[i] = *(const float4*)&B[(size_t)(idx >> 5) * N + col0 + (idx & 31) * 4];
    }
    #pragma unroll
    for (int i = 0; i < 4; i++) {
        const int idx = tid + i * 256;
        uint32_t* p = As + (idx >> 3) * AS_STRIDE + (idx & 7) * 4;
        p[0] = f2tf32(pa[i].x); p[1] = f2tf32(pa[i].y);
        p[2] = f2tf32(pa[i].z); p[3] = f2tf32(pa[i].w);
        uint32_t* q = Bs + (idx >> 5) * BS_STRIDE + (idx & 31) * 4;
        q[0] = f2tf32(pb[i].x); q[1] = f2tf32(pb[i].y);
        q[2] = f2tf32(pb[i].z); q[3] = f2tf32(pb[i].w);
    }
    __syncthreads();

    float c[4][4][4] = {};
    const int nkt = K >> 5;
    int buf = 0;

    for (int t = 0; t < nkt; t++) {
        if (t + 1 < nkt) {
            const int k0 = (t + 1) * 32;
            #pragma unroll
            for (int i = 0; i < 4; i++) {
                const int idx = tid + i * 256;
                pa[i] = *(const float4*)&A[(size_t)(row0 + (idx >> 3)) * K + k0 + (idx & 7) * 4];
                pb[i] = *(const float4*)&B[(size_t)(k0 + (idx >> 5)) * N + col0 + (idx & 31) * 4];
            }
        }

        #pragma unroll
        for (int ks = 0; ks < 4; ks++) {
            uint32_t af[4][4], bf[4][2];
            const uint32_t* Ab = As + buf * AS_TILE + (wm + gid) * AS_STRIDE + ks * 8 + tig;
            #pragma unroll
            for (int mt = 0; mt < 4; mt++) {
                const uint32_t* p = Ab + mt * 16 * AS_STRIDE;
                af[mt][0] = p[0];
                af[mt][1] = p[8 * AS_STRIDE];
                af[mt][2] = p[4];
                af[mt][3] = p[8 * AS_STRIDE + 4];
            }
            const uint32_t* Bb = Bs + buf * BS_TILE + (ks * 8 + tig) * BS_STRIDE + wn + gid;
            #pragma unroll
            for (int nt = 0; nt < 4; nt++) {
                const uint32_t* p = Bb + nt * 8;
                bf[nt][0] = p[0];
                bf[nt][1] = p[4 * BS_STRIDE];
            }
            #pragma unroll
            for (int mt = 0; mt < 4; mt++)
                #pragma unroll
                for (int nt = 0; nt < 4; nt++)
                    mma_tf32(c[mt][nt], af[mt], bf[nt]);
        }

        if (t + 1 < nkt) {
            buf ^= 1;
            #pragma unroll
            for (int i = 0; i < 4; i++) {
                const int idx = tid + i * 256;
                uint32_t* p = As + buf * AS_TILE + (idx >> 3) * AS_STRIDE + (idx & 7) * 4;
                p[0] = f2tf32(pa[i].x); p[1] = f2tf32(pa[i].y);
                p[2] = f2tf32(pa[i].z); p[3] = f2tf32(pa[i].w);
                uint32_t* q = Bs + buf * BS_TILE + (idx >> 5) * BS_STRIDE + (idx & 31) * 4;
                q[0] = f2tf32(pb[i].x); q[1] = f2tf32(pb[i].y);
                q[2] = f2tf32(pb[i].z); q[3] = f2tf32(pb[i].w);
            }
            __syncthreads();
        }
    }

    #pragma unroll
    for (int nt = 0; nt < 4; nt++) {
        const int cc = col0 + wn + nt * 8 + 2 * tig;
        const float b0 = bias ? bias[cc]     : 0.f;
        const float b1 = bias ? bias[cc + 1] : 0.f;
        #pragma unroll
        for (int mt = 0; mt < 4; mt++) {
            const int r = row0 + wm + mt * 16 + gid;
            float2 v0 = make_float2(c[mt][nt][0] + b0, c[mt][nt][1] + b1);
            float2 v1 = make_float2(c[mt][nt][2] + b0, c[mt][nt][3] + b1);
            *(float2*)&C[(size_t)r * N + cc]       = v0;
            *(float2*)&C[(size_t)(r + 8) * N + cc] = v1;
        }
    }
}

// ---------------------------------------------------------------------------
// FA2-style tensor-core causal flash attention. 512 threads = 16 warps.
// Q tile 256 rows; warp tile = 16 rows x ALL 64 cols -> softmax is warp-
// private (quad shuffles only), P stays in registers (quad-shuffle c->a
// fragment conversion), no S/P smem round trips, 2 block syncs per K-tile.
// K/Q/V stored in k-permuted smem ([k0 k4 k1 k5 k2 k6 k3 k7] per 8-block) so
// each mma fragment pair (k,k+4) is one LDS.64. K/V prefetched into registers
// one tile ahead to hide LDG latency.
// ---------------------------------------------------------------------------
#define FSTR 68
#define QROWS 256
#define FLASH_SMEM ((QROWS * FSTR + 64 * FSTR + 64 * FSTR) * 4)  // 104448 B

__global__ __launch_bounds__(512) void flash_mma(const float* __restrict__ qkv,
                                                 float* __restrict__ out)
{
    extern __shared__ uint32_t smu[];
    uint32_t* Qt = smu;                  // [256][FSTR] tf32, k-permuted cols
    uint32_t* Kt = Qt + QROWS * FSTR;    // [64 j][FSTR] tf32, k(d)-permuted
    uint32_t* Vt = Kt + 64 * FSTR;       // [64 d][FSTR] tf32, k(j)-permuted

    const int tid  = threadIdx.x;
    const int lane = tid & 31;
    const int wid  = tid >> 5;          // 0..15
    const int wm   = wid * 16;          // warp's 16 query rows
    const int gid  = lane >> 2;
    const int tig  = lane & 3;
    const int qt   = gridDim.x - 1 - blockIdx.x;  // heavy blocks first
    const int h    = blockIdx.y;
    const int b    = blockIdx.z;

    // --- load Q tile (256 rows), scale, tf32, k-permuted store ---
    {
        const int r  = tid & 255;
        const int cg = tid >> 8;        // 0..1
        const float* qrow = qkv + ((size_t)(b * SEQ + qt * QROWS + r)) * QKV_N + h * HEAD_DIM;
        #pragma unroll
        for (int it = 0; it < 8; it++) {
            const int d4 = cg * 32 + it * 4;
            float4 v = *(const float4*)(qrow + d4);
            uint32_t* p = Qt + r * FSTR + (d4 & ~7) + ((d4 >> 2) & 1);
            p[0] = f2tf32(v.x * SCALE);
            p[2] = f2tf32(v.y * SCALE);
            p[4] = f2tf32(v.z * SCALE);
            p[6] = f2tf32(v.w * SCALE);
        }
    }

    // --- K/V register prefetch state ---
    const int r63 = tid & 63;
    const int cg0 = tid >> 6;           // 0..7
    float4 ka[2], va[2];
    {
        const float* kb = qkv + ((size_t)(b * SEQ + r63)) * QKV_N + D_MODEL + h * HEAD_DIM;
        #pragma unroll
        for (int it = 0; it < 2; it++) {
            const int d4 = cg0 * 4 + it * 32;
            ka[it] = *(const float4*)(kb + d4);
            va[it] = *(const float4*)(kb + D_MODEL + d4);
        }
    }

    float co[8][4] = {};    // O fragments: 8 n(d)-tiles
    float m0 = -1e30f, m1 = -1e30f, l0 = 0.f, l1 = 0.f;
    const int r0 = qt * QROWS + wm + gid;
    const int r1 = r0 + 8;
    const int ktmax = 4 * qt + 3;

    for (int kt = 0; kt <= ktmax; kt++) {
        __syncthreads();  // previous tile's consumers done with Kt/Vt

        // store prefetched K/V into permuted smem
        #pragma unroll
        for (int it = 0; it < 2; it++) {
            const int d4 = cg0 * 4 + it * 32;
            uint32_t* p = Kt + r63 * FSTR + (d4 & ~7) + ((d4 >> 2) & 1);
            p[0] = f2tf32(ka[it].x);
            p[2] = f2tf32(ka[it].y);
            p[4] = f2tf32(ka[it].z);
            p[6] = f2tf32(ka[it].w);
            const int jp = (r63 & ~7) + 2 * (r63 & 3) + ((r63 >> 2) & 1);
            Vt[(d4 + 0) * FSTR + jp] = f2tf32(va[it].x);
            Vt[(d4 + 1) * FSTR + jp] = f2tf32(va[it].y);
            Vt[(d4 + 2) * FSTR + jp] = f2tf32(va[it].z);
            Vt[(d4 + 3) * FSTR + jp] = f2tf32(va[it].w);
        }
        __syncthreads();

        // prefetch next K/V tile into registers (latency hidden behind compute)
        if (kt < ktmax) {
            const float* kb = qkv + ((size_t)(b * SEQ + (kt + 1) * 64 + r63)) * QKV_N
                              + D_MODEL + h * HEAD_DIM;
            #pragma unroll
            for (int it = 0; it < 2; it++) {
                const int d4 = cg0 * 4 + it * 32;
                ka[it] = *(const float4*)(kb + d4);
                va[it] = *(const float4*)(kb + D_MODEL + d4);
            }
        }

        // --- S = (Q*SCALE) K^T : warp-private 16x64 ---
        float cs[8][4] = {};
        #pragma unroll
        for (int ks = 0; ks < 8; ks++) {
            uint32_t af[4];
            const uint2 qlo = *(const uint2*)&Qt[(wm + gid) * FSTR + ks * 8 + 2 * tig];
            const uint2 qhi = *(const uint2*)&Qt[(wm + gid + 8) * FSTR + ks * 8 + 2 * tig];
            af[0] = qlo.x; af[1] = qhi.x; af[2] = qlo.y; af[3] = qhi.y;
            #pragma unroll
            for (int nt = 0; nt < 8; nt++) {
                const uint2 kb2 = *(const uint2*)&Kt[(nt * 8 + gid) * FSTR + ks * 8 + 2 * tig];
                uint32_t bf[2] = { kb2.x, kb2.y };
                mma_tf32(cs[nt], af, bf);
            }
        }

        // --- causal mask (only tiles in the diagonal band) ---
        if (kt >= 4 * qt) {
            #pragma unroll
            for (int nt = 0; nt < 8; nt++) {
                const int j0 = kt * 64 + nt * 8 + 2 * tig;
                if (j0     > r0) cs[nt][0] = -1e30f;
                if (j0 + 1 > r0) cs[nt][1] = -1e30f;
                if (j0     > r1) cs[nt][2] = -1e30f;
                if (j0 + 1 > r1) cs[nt][3] = -1e30f;
            }
        }

        // --- warp-private online softmax (quad reduction only) ---
        float tm0 = -1e30f, tm1 = -1e30f;
        #pragma unroll
        for (int nt = 0; nt < 8; nt++) {
            tm0 = fmaxf(tm0, fmaxf(cs[nt][0], cs[nt][1]));
            tm1 = fmaxf(tm1, fmaxf(cs[nt][2], cs[nt][3]));
        }
        tm0 = fmaxf(tm0, __shfl_xor_sync(0xFFFFFFFFu, tm0, 1));
        tm0 = fmaxf(tm0, __shfl_xor_sync(0xFFFFFFFFu, tm0, 2));
        tm1 = fmaxf(tm1, __shfl_xor_sync(0xFFFFFFFFu, tm1, 1));
        tm1 = fmaxf(tm1, __shfl_xor_sync(0xFFFFFFFFu, tm1, 2));

        const float mn0 = fmaxf(m0, tm0);
        const float mn1 = fmaxf(m1, tm1);
        const float al0 = __expf(m0 - mn0);
        const float al1 = __expf(m1 - mn1);
        m0 = mn0; m1 = mn1;

        float rs0 = 0.f, rs1 = 0.f;
        #pragma unroll
        for (int nt = 0; nt < 8; nt++) {
            cs[nt][0] = __expf(cs[nt][0] - mn0);
            cs[nt][1] = __expf(cs[nt][1] - mn0);
            cs[nt][2] = __expf(cs[nt][2] - mn1);
            cs[nt][3] = __expf(cs[nt][3] - mn1);
            rs0 += cs[nt][0] + cs[nt][1];
            rs1 += cs[nt][2] + cs[nt][3];
        }
        rs0 += __shfl_xor_sync(0xFFFFFFFFu, rs0, 1);
        rs0 += __shfl_xor_sync(0xFFFFFFFFu, rs0, 2);
        rs1 += __shfl_xor_sync(0xFFFFFFFFu, rs1, 1);
        rs1 += __shfl_xor_sync(0xFFFFFFFFu, rs1, 2);
        l0 = l0 * al0 + rs0;
        l1 = l1 * al1 + rs1;

        #pragma unroll
        for (int nt = 0; nt < 8; nt++) {
            co[nt][0] *= al0; co[nt][1] *= al0;
            co[nt][2] *= al1; co[nt][3] *= al1;
        }

        // --- O += P V: P fragments built via quad shuffles (no smem) ---
        const int qb   = lane & ~3;
        const int s_lo = qb + (tig >> 1);
        const int s_hi = s_lo + 2;
        const bool odd = tig & 1;
        #pragma unroll
        for (int ks = 0; ks < 8; ks++) {
            const float b00 = __shfl_sync(0xFFFFFFFFu, cs[ks][0], s_lo);
            const float b01 = __shfl_sync(0xFFFFFFFFu, cs[ks][1], s_lo);
            const float b10 = __shfl_sync(0xFFFFFFFFu, cs[ks][2], s_lo);
            const float b11 = __shfl_sync(0xFFFFFFFFu, cs[ks][3], s_lo);
            const float c00 = __shfl_sync(0xFFFFFFFFu, cs[ks][0], s_hi);
            const float c01 = __shfl_sync(0xFFFFFFFFu, cs[ks][1], s_hi);
            const float c10 = __shfl_sync(0xFFFFFFFFu, cs[ks][2], s_hi);
            const float c11 = __shfl_sync(0xFFFFFFFFu, cs[ks][3], s_hi);
            uint32_t pa[4];
            pa[0] = f2tf32(odd ? b01 : b00);   // P[gid  ][ks*8+tig]
            pa[1] = f2tf32(odd ? b11 : b10);   // P[gid+8][ks*8+tig]
            pa[2] = f2tf32(odd ? c01 : c00);   // P[gid  ][ks*8+tig+4]
            pa[3] = f2tf32(odd ? c11 : c10);   // P[gid+8][ks*8+tig+4]
            #pragma unroll
            for (int nt = 0; nt < 8; nt++) {
                const uint2 vb2 = *(const uint2*)&Vt[(nt * 8 + gid) * FSTR + ks * 8 + 2 * tig];
                uint32_t bf[2] = { vb2.x, vb2.y };
                mma_tf32(co[nt], pa, bf);
            }
        }
    }

    // --- epilogue ---
    const float inv0 = 1.f / l0;
    const float inv1 = 1.f / l1;
    float* ob = out + ((size_t)(b * SEQ + qt * QROWS)) * D_MODEL + h * HEAD_DIM;
    #pragma unroll
    for (int nt = 0; nt < 8; nt++) {
        const int cc = nt * 8 + 2 * tig;
        float2 v0 = make_float2(co[nt][0] * inv0, co[nt][1] * inv0);
        float2 v1 = make_float2(co[nt][2] * inv1, co[nt][3] * inv1);
        *(float2*)&ob[(size_t)(wm + gid) * D_MODEL + cc]     = v0;
        *(float2*)&ob[(size_t)(wm + gid + 8) * D_MODEL + cc] = v1;
    }
}

// ---------------------------------------------------------------------------
// Launch: tf32 QKV GEMM -> tf32 flash attention -> tf32 out projection (+bias)
// Inputs: x, attn_mask (ignored; causal known), W_qkv, W_proj, b_proj
// ---------------------------------------------------------------------------
extern "C" void kernel_launch(void* const* d_in, const int* in_sizes, int n_in,
                              void* d_out, int out_size)
{
    (void)in_sizes; (void)n_in; (void)out_size;
    const float* x      = (const float*)d_in[0];
    const float* W_qkv  = (const float*)d_in[2];
    const float* W_proj = (const float*)d_in[3];
    const float* b_proj = (const float*)d_in[4];
    float* out = (float*)d_out;

    float *qkv, *attn;
    cudaGetSymbolAddress((void**)&qkv,  g_qkv);
    cudaGetSymbolAddress((void**)&attn, g_attn);

    cudaFuncSetAttribute(gemm_tf32, cudaFuncAttributeMaxDynamicSharedMemorySize, GEMM_SMEM);
    cudaFuncSetAttribute(flash_mma, cudaFuncAttributeMaxDynamicSharedMemorySize, FLASH_SMEM);

    // 1) QKV projection: [4096,768] @ [768,2304]  (tf32 tensor cores)
    gemm_tf32<<<dim3(QKV_N / 128, M_TOK / 128), 256, GEMM_SMEM>>>(x, W_qkv, nullptr, qkv,
                                                                  M_TOK, QKV_N, D_MODEL);

    // 2) causal flash attention per (q-tile, head, batch)  (tf32 tensor cores)
    flash_mma<<<dim3(SEQ / QROWS, N_HEADS, BATCH), 512, FLASH_SMEM>>>(qkv, attn);

    // 3) output projection + bias: [4096,768] @ [768,768]  (tf32 tensor cores)
    gemm_tf32<<<dim3(D_MODEL / 128, M_TOK / 128), 256, GEMM_SMEM>>>(attn, W_proj, b_proj, out,
                                                                    M_TOK, D_MODEL, D_MODEL);
}

// round 10
// speedup vs baseline: 1.3283x; 1.2073x over previous
#include <cuda_runtime.h>
#include <math.h>
#include <stdint.h>

#define D_MODEL 768
#define N_HEADS 12
#define HEAD_DIM 64
#define SEQ 2048
#define BATCH 2
#define QKV_N (3 * D_MODEL)
#define M_TOK (BATCH * SEQ)
#define SCALE 0.125f

// Scratch (allocation-free rule: __device__ globals)
__device__ float g_qkv[(size_t)M_TOK * QKV_N];    // [B*S, 3*D] (Q | K | V)
__device__ float g_attn[(size_t)M_TOK * D_MODEL]; // [B*S, D] attention output

__device__ __forceinline__ uint32_t f2tf32(float x) {
    uint32_t r;
    asm("cvt.rna.tf32.f32 %0, %1;" : "=r"(r) : "f"(x));
    return r;
}

__device__ __forceinline__ void mma_tf32(float* c, const uint32_t* a, const uint32_t* b) {
    asm volatile("mma.sync.aligned.m16n8k8.row.col.f32.tf32.tf32.f32 "
                 "{%0,%1,%2,%3}, {%4,%5,%6,%7}, {%8,%9}, {%0,%1,%2,%3};"
                 : "+f"(c[0]), "+f"(c[1]), "+f"(c[2]), "+f"(c[3])
                 : "r"(a[0]), "r"(a[1]), "r"(a[2]), "r"(a[3]),
                   "r"(b[0]), "r"(b[1]));
}

// ---------------------------------------------------------------------------
// tf32 tensor-core GEMM: block 128x256, BK=16, 256 threads = 8 warps in a
// 2(M)x4(N) grid, warp tile 64x64 (4 m-frags x 8 n-frags). Double-buffered.
// 64x64 warp tile doubles MAC per smem byte vs 64x32 (crossbar was binding).
// ---------------------------------------------------------------------------
#define BKG 16
#define AS_STRIDE 20
#define BS_STRIDE 260
#define AS_TILE (128 * AS_STRIDE)   // 2560 words
#define BS_TILE (BKG * BS_STRIDE)   // 4160 words
#define GEMM_SMEM ((2 * AS_TILE + 2 * BS_TILE) * 4)  // 53760 B

__global__ __launch_bounds__(256) void gemm_tf32(const float* __restrict__ A,
                                                 const float* __restrict__ B,
                                                 const float* __restrict__ bias,
                                                 float* __restrict__ C,
                                                 int M, int N, int K)
{
    extern __shared__ uint32_t smu[];
    uint32_t* As = smu;               // [2][128][20]
    uint32_t* Bs = smu + 2 * AS_TILE; // [2][16][260]

    const int tid  = threadIdx.x;
    const int lane = tid & 31;
    const int wid  = tid >> 5;
    const int wm   = (wid & 1) * 64;
    const int wn   = (wid >> 1) * 64;
    const int row0 = blockIdx.y * 128;
    const int col0 = blockIdx.x * 256;
    const int gid  = lane >> 2;
    const int tig  = lane & 3;

    // A: 128x16 -> 512 float4, 2/thread. row = idx>>2, k4 = (idx&3)*4
    // B: 16x256 -> 1024 float4, 4/thread. k = idx>>6, n4 = (idx&63)*4
    float4 pa[2], pb[4];

    #pragma unroll
    for (int i = 0; i < 2; i++) {
        const int idx = tid + i * 256;
        pa[i] = *(const float4*)&A[(size_t)(row0 + (idx >> 2)) * K + (idx & 3) * 4];
    }
    #pragma unroll
    for (int i = 0; i < 4; i++) {
        const int idx = tid + i * 256;
        pb[i] = *(const float4*)&B[(size_t)(idx >> 6) * N + col0 + (idx & 63) * 4];
    }
    #pragma unroll
    for (int i = 0; i < 2; i++) {
        const int idx = tid + i * 256;
        uint32_t* p = As + (idx >> 2) * AS_STRIDE + (idx & 3) * 4;
        p[0] = f2tf32(pa[i].x); p[1] = f2tf32(pa[i].y);
        p[2] = f2tf32(pa[i].z); p[3] = f2tf32(pa[i].w);
    }
    #pragma unroll
    for (int i = 0; i < 4; i++) {
        const int idx = tid + i * 256;
        uint32_t* q = Bs + (idx >> 6) * BS_STRIDE + (idx & 63) * 4;
        q[0] = f2tf32(pb[i].x); q[1] = f2tf32(pb[i].y);
        q[2] = f2tf32(pb[i].z); q[3] = f2tf32(pb[i].w);
    }
    __syncthreads();

    float c[4][8][4] = {};
    const int nkt = K / BKG;
    int buf = 0;

    for (int t = 0; t < nkt; t++) {
        if (t + 1 < nkt) {
            const int k0 = (t + 1) * BKG;
            #pragma unroll
            for (int i = 0; i < 2; i++) {
                const int idx = tid + i * 256;
                pa[i] = *(const float4*)&A[(size_t)(row0 + (idx >> 2)) * K + k0 + (idx & 3) * 4];
            }
            #pragma unroll
            for (int i = 0; i < 4; i++) {
                const int idx = tid + i * 256;
                pb[i] = *(const float4*)&B[(size_t)(k0 + (idx >> 6)) * N + col0 + (idx & 63) * 4];
            }
        }

        #pragma unroll
        for (int ks = 0; ks < 2; ks++) {
            uint32_t af[4][4], bf[8][2];
            const uint32_t* Ab = As + buf * AS_TILE + (wm + gid) * AS_STRIDE + ks * 8 + tig;
            #pragma unroll
            for (int mt = 0; mt < 4; mt++) {
                const uint32_t* p = Ab + mt * 16 * AS_STRIDE;
                af[mt][0] = p[0];
                af[mt][1] = p[8 * AS_STRIDE];
                af[mt][2] = p[4];
                af[mt][3] = p[8 * AS_STRIDE + 4];
            }
            const uint32_t* Bb = Bs + buf * BS_TILE + (ks * 8 + tig) * BS_STRIDE + wn + gid;
            #pragma unroll
            for (int nt = 0; nt < 8; nt++) {
                const uint32_t* p = Bb + nt * 8;
                bf[nt][0] = p[0];
                bf[nt][1] = p[4 * BS_STRIDE];
            }
            #pragma unroll
            for (int mt = 0; mt < 4; mt++)
                #pragma unroll
                for (int nt = 0; nt < 8; nt++)
                    mma_tf32(c[mt][nt], af[mt], bf[nt]);
        }

        if (t + 1 < nkt) {
            buf ^= 1;
            #pragma unroll
            for (int i = 0; i < 2; i++) {
                const int idx = tid + i * 256;
                uint32_t* p = As + buf * AS_TILE + (idx >> 2) * AS_STRIDE + (idx & 3) * 4;
                p[0] = f2tf32(pa[i].x); p[1] = f2tf32(pa[i].y);
                p[2] = f2tf32(pa[i].z); p[3] = f2tf32(pa[i].w);
            }
            #pragma unroll
            for (int i = 0; i < 4; i++) {
                const int idx = tid + i * 256;
                uint32_t* q = Bs + buf * BS_TILE + (idx >> 6) * BS_STRIDE + (idx & 63) * 4;
                q[0] = f2tf32(pb[i].x); q[1] = f2tf32(pb[i].y);
                q[2] = f2tf32(pb[i].z); q[3] = f2tf32(pb[i].w);
            }
            __syncthreads();
        }
    }

    #pragma unroll
    for (int nt = 0; nt < 8; nt++) {
        const int cc = col0 + wn + nt * 8 + 2 * tig;
        const float b0 = bias ? bias[cc]     : 0.f;
        const float b1 = bias ? bias[cc + 1] : 0.f;
        #pragma unroll
        for (int mt = 0; mt < 4; mt++) {
            const int r = row0 + wm + mt * 16 + gid;
            float2 v0 = make_float2(c[mt][nt][0] + b0, c[mt][nt][1] + b1);
            float2 v1 = make_float2(c[mt][nt][2] + b0, c[mt][nt][3] + b1);
            *(float2*)&C[(size_t)r * N + cc]       = v0;
            *(float2*)&C[(size_t)(r + 8) * N + cc] = v1;
        }
    }
}

// ---------------------------------------------------------------------------
// FA2-style tensor-core causal flash attention. 256 threads = 8 warps.
// Q tile 256 rows; warp tile = 32 rows x 64 cols (2 m-subtiles sharing every
// K/V fragment load -> K/V smem traffic halves vs 16-row warps). Softmax is
// warp-private; P stays in registers via quad-shuffle c->a conversion.
// k-permuted smem so fragment pairs are LDS.64. K/V prefetched one tile ahead.
// ---------------------------------------------------------------------------
#define FSTR 68
#define QROWS 256
#define FLASH_SMEM ((QROWS * FSTR + 64 * FSTR + 64 * FSTR) * 4)  // 104448 B

__global__ __launch_bounds__(256) void flash_mma(const float* __restrict__ qkv,
                                                 float* __restrict__ out)
{
    extern __shared__ uint32_t smu[];
    uint32_t* Qt = smu;                  // [256][FSTR] tf32, k-permuted cols
    uint32_t* Kt = Qt + QROWS * FSTR;    // [64 j][FSTR] tf32, k(d)-permuted
    uint32_t* Vt = Kt + 64 * FSTR;       // [64 d][FSTR] tf32, k(j)-permuted

    const int tid  = threadIdx.x;
    const int lane = tid & 31;
    const int wid  = tid >> 5;          // 0..7
    const int wm   = wid * 32;          // warp's 32 query rows
    const int gid  = lane >> 2;
    const int tig  = lane & 3;
    const int qt   = gridDim.x - 1 - blockIdx.x;  // heavy blocks first
    const int h    = blockIdx.y;
    const int b    = blockIdx.z;

    // --- load Q tile (256 rows, 1 thread/row), scale, tf32, k-permuted ---
    {
        const float* qrow = qkv + ((size_t)(b * SEQ + qt * QROWS + tid)) * QKV_N + h * HEAD_DIM;
        #pragma unroll
        for (int it = 0; it < 16; it++) {
            const int d4 = it * 4;
            float4 v = *(const float4*)(qrow + d4);
            uint32_t* p = Qt + tid * FSTR + (d4 & ~7) + ((d4 >> 2) & 1);
            p[0] = f2tf32(v.x * SCALE);
            p[2] = f2tf32(v.y * SCALE);
            p[4] = f2tf32(v.z * SCALE);
            p[6] = f2tf32(v.w * SCALE);
        }
    }

    // --- K/V register prefetch (4 threads/row, 16 el each) ---
    const int r63 = tid & 63;
    const int cg0 = tid >> 6;           // 0..3
    float4 ka[4], va[4];
    {
        const float* kb = qkv + ((size_t)(b * SEQ + r63)) * QKV_N + D_MODEL + h * HEAD_DIM;
        #pragma unroll
        for (int it = 0; it < 4; it++) {
            const int d4 = cg0 * 16 + it * 4;
            ka[it] = *(const float4*)(kb + d4);
            va[it] = *(const float4*)(kb + D_MODEL + d4);
        }
    }

    float co[2][8][4] = {};    // O fragments: 2 m-subtiles x 8 d-tiles
    float m[4], l[4];          // rows: [s*2+g] = subtile s, row-group g (gid / gid+8)
    #pragma unroll
    for (int i = 0; i < 4; i++) { m[i] = -1e30f; l[i] = 0.f; }

    const int rbase = qt * QROWS + wm + gid;
    const int ktmax = 4 * qt + 3;

    for (int kt = 0; kt <= ktmax; kt++) {
        __syncthreads();  // previous tile's consumers done with Kt/Vt

        // store prefetched K/V into permuted smem
        #pragma unroll
        for (int it = 0; it < 4; it++) {
            const int d4 = cg0 * 16 + it * 4;
            uint32_t* p = Kt + r63 * FSTR + (d4 & ~7) + ((d4 >> 2) & 1);
            p[0] = f2tf32(ka[it].x);
            p[2] = f2tf32(ka[it].y);
            p[4] = f2tf32(ka[it].z);
            p[6] = f2tf32(ka[it].w);
            const int jp = (r63 & ~7) + 2 * (r63 & 3) + ((r63 >> 2) & 1);
            Vt[(d4 + 0) * FSTR + jp] = f2tf32(va[it].x);
            Vt[(d4 + 1) * FSTR + jp] = f2tf32(va[it].y);
            Vt[(d4 + 2) * FSTR + jp] = f2tf32(va[it].z);
            Vt[(d4 + 3) * FSTR + jp] = f2tf32(va[it].w);
        }
        __syncthreads();

        // prefetch next K/V tile into registers
        if (kt < ktmax) {
            const float* kb = qkv + ((size_t)(b * SEQ + (kt + 1) * 64 + r63)) * QKV_N
                              + D_MODEL + h * HEAD_DIM;
            #pragma unroll
            for (int it = 0; it < 4; it++) {
                const int d4 = cg0 * 16 + it * 4;
                ka[it] = *(const float4*)(kb + d4);
                va[it] = *(const float4*)(kb + D_MODEL + d4);
            }
        }

        // --- S = (Q*SCALE) K^T : 32x64 per warp, K frags shared by subtiles ---
        float cs[2][8][4] = {};
        #pragma unroll
        for (int ks = 0; ks < 8; ks++) {
            uint32_t af[2][4];
            #pragma unroll
            for (int s = 0; s < 2; s++) {
                const uint2 qlo = *(const uint2*)&Qt[(wm + s * 16 + gid) * FSTR + ks * 8 + 2 * tig];
                const uint2 qhi = *(const uint2*)&Qt[(wm + s * 16 + gid + 8) * FSTR + ks * 8 + 2 * tig];
                af[s][0] = qlo.x; af[s][1] = qhi.x; af[s][2] = qlo.y; af[s][3] = qhi.y;
            }
            #pragma unroll
            for (int nt = 0; nt < 8; nt++) {
                const uint2 kb2 = *(const uint2*)&Kt[(nt * 8 + gid) * FSTR + ks * 8 + 2 * tig];
                uint32_t bf[2] = { kb2.x, kb2.y };
                mma_tf32(cs[0][nt], af[0], bf);
                mma_tf32(cs[1][nt], af[1], bf);
            }
        }

        // --- causal mask (tiles in the diagonal band only) ---
        if (kt >= 4 * qt) {
            #pragma unroll
            for (int s = 0; s < 2; s++) {
                const int r0 = rbase + s * 16;
                const int r1 = r0 + 8;
                #pragma unroll
                for (int nt = 0; nt < 8; nt++) {
                    const int j0 = kt * 64 + nt * 8 + 2 * tig;
                    if (j0     > r0) cs[s][nt][0] = -1e30f;
                    if (j0 + 1 > r0) cs[s][nt][1] = -1e30f;
                    if (j0     > r1) cs[s][nt][2] = -1e30f;
                    if (j0 + 1 > r1) cs[s][nt][3] = -1e30f;
                }
            }
        }

        // --- warp-private online softmax (quad reduction only) ---
        #pragma unroll
        for (int s = 0; s < 2; s++) {
            float tm0 = -1e30f, tm1 = -1e30f;
            #pragma unroll
            for (int nt = 0; nt < 8; nt++) {
                tm0 = fmaxf(tm0, fmaxf(cs[s][nt][0], cs[s][nt][1]));
                tm1 = fmaxf(tm1, fmaxf(cs[s][nt][2], cs[s][nt][3]));
            }
            tm0 = fmaxf(tm0, __shfl_xor_sync(0xFFFFFFFFu, tm0, 1));
            tm0 = fmaxf(tm0, __shfl_xor_sync(0xFFFFFFFFu, tm0, 2));
            tm1 = fmaxf(tm1, __shfl_xor_sync(0xFFFFFFFFu, tm1, 1));
            tm1 = fmaxf(tm1, __shfl_xor_sync(0xFFFFFFFFu, tm1, 2));

            const float mn0 = fmaxf(m[s * 2 + 0], tm0);
            const float mn1 = fmaxf(m[s * 2 + 1], tm1);
            const float al0 = __expf(m[s * 2 + 0] - mn0);
            const float al1 = __expf(m[s * 2 + 1] - mn1);
            m[s * 2 + 0] = mn0; m[s * 2 + 1] = mn1;

            float rs0 = 0.f, rs1 = 0.f;
            #pragma unroll
            for (int nt = 0; nt < 8; nt++) {
                cs[s][nt][0] = __expf(cs[s][nt][0] - mn0);
                cs[s][nt][1] = __expf(cs[s][nt][1] - mn0);
                cs[s][nt][2] = __expf(cs[s][nt][2] - mn1);
                cs[s][nt][3] = __expf(cs[s][nt][3] - mn1);
                rs0 += cs[s][nt][0] + cs[s][nt][1];
                rs1 += cs[s][nt][2] + cs[s][nt][3];
            }
            rs0 += __shfl_xor_sync(0xFFFFFFFFu, rs0, 1);
            rs0 += __shfl_xor_sync(0xFFFFFFFFu, rs0, 2);
            rs1 += __shfl_xor_sync(0xFFFFFFFFu, rs1, 1);
            rs1 += __shfl_xor_sync(0xFFFFFFFFu, rs1, 2);
            l[s * 2 + 0] = l[s * 2 + 0] * al0 + rs0;
            l[s * 2 + 1] = l[s * 2 + 1] * al1 + rs1;

            #pragma unroll
            for (int nt = 0; nt < 8; nt++) {
                co[s][nt][0] *= al0; co[s][nt][1] *= al0;
                co[s][nt][2] *= al1; co[s][nt][3] *= al1;
            }
        }

        // --- O += P V: P frags via quad shuffles, V frags shared by subtiles ---
        const int qb   = lane & ~3;
        const int s_lo = qb + (tig >> 1);
        const int s_hi = s_lo + 2;
        const bool odd = tig & 1;
        #pragma unroll
        for (int ks = 0; ks < 8; ks++) {
            uint32_t pa[2][4];
            #pragma unroll
            for (int s = 0; s < 2; s++) {
                const float b00 = __shfl_sync(0xFFFFFFFFu, cs[s][ks][0], s_lo);
                const float b01 = __shfl_sync(0xFFFFFFFFu, cs[s][ks][1], s_lo);
                const float b10 = __shfl_sync(0xFFFFFFFFu, cs[s][ks][2], s_lo);
                const float b11 = __shfl_sync(0xFFFFFFFFu, cs[s][ks][3], s_lo);
                const float c00 = __shfl_sync(0xFFFFFFFFu, cs[s][ks][0], s_hi);
                const float c01 = __shfl_sync(0xFFFFFFFFu, cs[s][ks][1], s_hi);
                const float c10 = __shfl_sync(0xFFFFFFFFu, cs[s][ks][2], s_hi);
                const float c11 = __shfl_sync(0xFFFFFFFFu, cs[s][ks][3], s_hi);
                pa[s][0] = f2tf32(odd ? b01 : b00);
                pa[s][1] = f2tf32(odd ? b11 : b10);
                pa[s][2] = f2tf32(odd ? c01 : c00);
                pa[s][3] = f2tf32(odd ? c11 : c10);
            }
            #pragma unroll
            for (int nt = 0; nt < 8; nt++) {
                const uint2 vb2 = *(const uint2*)&Vt[(nt * 8 + gid) * FSTR + ks * 8 + 2 * tig];
                uint32_t bf[2] = { vb2.x, vb2.y };
                mma_tf32(co[0][nt], pa[0], bf);
                mma_tf32(co[1][nt], pa[1], bf);
            }
        }
    }

    // --- epilogue ---
    float* ob = out + ((size_t)(b * SEQ + qt * QROWS)) * D_MODEL + h * HEAD_DIM;
    #pragma unroll
    for (int s = 0; s < 2; s++) {
        const float inv0 = 1.f / l[s * 2 + 0];
        const float inv1 = 1.f / l[s * 2 + 1];
        #pragma unroll
        for (int nt = 0; nt < 8; nt++) {
            const int cc = nt * 8 + 2 * tig;
            float2 v0 = make_float2(co[s][nt][0] * inv0, co[s][nt][1] * inv0);
            float2 v1 = make_float2(co[s][nt][2] * inv1, co[s][nt][3] * inv1);
            *(float2*)&ob[(size_t)(wm + s * 16 + gid) * D_MODEL + cc]     = v0;
            *(float2*)&ob[(size_t)(wm + s * 16 + gid + 8) * D_MODEL + cc] = v1;
        }
    }
}

// ---------------------------------------------------------------------------
// Launch: tf32 QKV GEMM -> tf32 flash attention -> tf32 out projection (+bias)
// Inputs: x, attn_mask (ignored; causal known), W_qkv, W_proj, b_proj
// ---------------------------------------------------------------------------
extern "C" void kernel_launch(void* const* d_in, const int* in_sizes, int n_in,
                              void* d_out, int out_size)
{
    (void)in_sizes; (void)n_in; (void)out_size;
    const float* x      = (const float*)d_in[0];
    const float* W_qkv  = (const float*)d_in[2];
    const float* W_proj = (const float*)d_in[3];
    const float* b_proj = (const float*)d_in[4];
    float* out = (float*)d_out;

    float *qkv, *attn;
    cudaGetSymbolAddress((void**)&qkv,  g_qkv);
    cudaGetSymbolAddress((void**)&attn, g_attn);

    cudaFuncSetAttribute(gemm_tf32, cudaFuncAttributeMaxDynamicSharedMemorySize, GEMM_SMEM);
    cudaFuncSetAttribute(flash_mma, cudaFuncAttributeMaxDynamicSharedMemorySize, FLASH_SMEM);

    // 1) QKV projection: [4096,768] @ [768,2304]  (tf32 tensor cores)
    gemm_tf32<<<dim3(QKV_N / 256, M_TOK / 128), 256, GEMM_SMEM>>>(x, W_qkv, nullptr, qkv,
                                                                  M_TOK, QKV_N, D_MODEL);

    // 2) causal flash attention per (q-tile, head, batch)  (tf32 tensor cores)
    flash_mma<<<dim3(SEQ / QROWS, N_HEADS, BATCH), 256, FLASH_SMEM>>>(qkv, attn);

    // 3) output projection + bias: [4096,768] @ [768,768]  (tf32 tensor cores)
    gemm_tf32<<<dim3(D_MODEL / 256, M_TOK / 128), 256, GEMM_SMEM>>>(attn, W_proj, b_proj, out,
                                                                    M_TOK, D_MODEL, D_MODEL);
}

// round 11
// speedup vs baseline: 1.4439x; 1.0870x over previous
#include <cuda_runtime.h>
#include <math.h>
#include <stdint.h>

#define D_MODEL 768
#define N_HEADS 12
#define HEAD_DIM 64
#define SEQ 2048
#define BATCH 2
#define QKV_N (3 * D_MODEL)
#define M_TOK (BATCH * SEQ)
#define SCALE 0.125f
#define SCALE_LOG2E 0.18033688011112042f   // 0.125 * log2(e)

// Scratch (allocation-free rule: __device__ globals)
__device__ float g_qkv[(size_t)M_TOK * QKV_N];    // [B*S, 3*D] (Q | K | V)
__device__ float g_attn[(size_t)M_TOK * D_MODEL]; // [B*S, D] attention output

__device__ __forceinline__ uint32_t f2tf32(float x) {
    uint32_t r;
    asm("cvt.rna.tf32.f32 %0, %1;" : "=r"(r) : "f"(x));
    return r;
}

__device__ __forceinline__ float fexp2(float x) {
    float r;
    asm("ex2.approx.f32 %0, %1;" : "=f"(r) : "f"(x));
    return r;
}

__device__ __forceinline__ void mma_tf32(float* c, const uint32_t* a, const uint32_t* b) {
    asm volatile("mma.sync.aligned.m16n8k8.row.col.f32.tf32.tf32.f32 "
                 "{%0,%1,%2,%3}, {%4,%5,%6,%7}, {%8,%9}, {%0,%1,%2,%3};"
                 : "+f"(c[0]), "+f"(c[1]), "+f"(c[2]), "+f"(c[3])
                 : "r"(a[0]), "r"(a[1]), "r"(a[2]), "r"(a[3]),
                   "r"(b[0]), "r"(b[1]));
}

// ---------------------------------------------------------------------------
// tf32 tensor-core GEMM: block 128x128x16, 128 threads = 4 warps in a
// 2(M)x2(N) grid, warp tile 64x64. Small block -> 2 independent blocks/SM:
// one block's sync/LDG bubble overlaps the other's mma work.
// ---------------------------------------------------------------------------
#define BKG 16
#define AS_STRIDE 20
#define BS_STRIDE 132
#define AS_TILE (128 * AS_STRIDE)   // 2560 words
#define BS_TILE (BKG * BS_STRIDE)   // 2112 words
#define GEMM_SMEM ((2 * AS_TILE + 2 * BS_TILE) * 4)  // 37376 B

__global__ __launch_bounds__(128) void gemm_tf32(const float* __restrict__ A,
                                                 const float* __restrict__ B,
                                                 const float* __restrict__ bias,
                                                 float* __restrict__ C,
                                                 int M, int N, int K)
{
    extern __shared__ uint32_t smu[];
    uint32_t* As = smu;               // [2][128][20]
    uint32_t* Bs = smu + 2 * AS_TILE; // [2][16][132]

    const int tid  = threadIdx.x;
    const int lane = tid & 31;
    const int wid  = tid >> 5;        // 0..3
    const int wm   = (wid & 1) * 64;
    const int wn   = (wid >> 1) * 64;
    const int row0 = blockIdx.y * 128;
    const int col0 = blockIdx.x * 128;
    const int gid  = lane >> 2;
    const int tig  = lane & 3;

    // A: 128x16 = 512 float4, 4/thread. row = idx>>2, k4 = (idx&3)*4
    // B: 16x128 = 512 float4, 4/thread. k = idx>>5, n4 = (idx&31)*4
    float4 pa[4], pb[4];

    #pragma unroll
    for (int i = 0; i < 4; i++) {
        const int idx = tid + i * 128;
        pa[i] = *(const float4*)&A[(size_t)(row0 + (idx >> 2)) * K + (idx & 3) * 4];
        pb[i] = *(const float4*)&B[(size_t)(idx >> 5) * N + col0 + (idx & 31) * 4];
    }
    #pragma unroll
    for (int i = 0; i < 4; i++) {
        const int idx = tid + i * 128;
        uint32_t* p = As + (idx >> 2) * AS_STRIDE + (idx & 3) * 4;
        p[0] = f2tf32(pa[i].x); p[1] = f2tf32(pa[i].y);
        p[2] = f2tf32(pa[i].z); p[3] = f2tf32(pa[i].w);
        uint32_t* q = Bs + (idx >> 5) * BS_STRIDE + (idx & 31) * 4;
        q[0] = f2tf32(pb[i].x); q[1] = f2tf32(pb[i].y);
        q[2] = f2tf32(pb[i].z); q[3] = f2tf32(pb[i].w);
    }
    __syncthreads();

    float c[4][8][4] = {};
    const int nkt = K / BKG;
    int buf = 0;

    for (int t = 0; t < nkt; t++) {
        if (t + 1 < nkt) {
            const int k0 = (t + 1) * BKG;
            #pragma unroll
            for (int i = 0; i < 4; i++) {
                const int idx = tid + i * 128;
                pa[i] = *(const float4*)&A[(size_t)(row0 + (idx >> 2)) * K + k0 + (idx & 3) * 4];
                pb[i] = *(const float4*)&B[(size_t)(k0 + (idx >> 5)) * N + col0 + (idx & 31) * 4];
            }
        }

        #pragma unroll
        for (int ks = 0; ks < 2; ks++) {
            uint32_t af[4][4], bf[8][2];
            const uint32_t* Ab = As + buf * AS_TILE + (wm + gid) * AS_STRIDE + ks * 8 + tig;
            #pragma unroll
            for (int mt = 0; mt < 4; mt++) {
                const uint32_t* p = Ab + mt * 16 * AS_STRIDE;
                af[mt][0] = p[0];
                af[mt][1] = p[8 * AS_STRIDE];
                af[mt][2] = p[4];
                af[mt][3] = p[8 * AS_STRIDE + 4];
            }
            const uint32_t* Bb = Bs + buf * BS_TILE + (ks * 8 + tig) * BS_STRIDE + wn + gid;
            #pragma unroll
            for (int nt = 0; nt < 8; nt++) {
                const uint32_t* p = Bb + nt * 8;
                bf[nt][0] = p[0];
                bf[nt][1] = p[4 * BS_STRIDE];
            }
            #pragma unroll
            for (int mt = 0; mt < 4; mt++)
                #pragma unroll
                for (int nt = 0; nt < 8; nt++)
                    mma_tf32(c[mt][nt], af[mt], bf[nt]);
        }

        if (t + 1 < nkt) {
            buf ^= 1;
            #pragma unroll
            for (int i = 0; i < 4; i++) {
                const int idx = tid + i * 128;
                uint32_t* p = As + buf * AS_TILE + (idx >> 2) * AS_STRIDE + (idx & 3) * 4;
                p[0] = f2tf32(pa[i].x); p[1] = f2tf32(pa[i].y);
                p[2] = f2tf32(pa[i].z); p[3] = f2tf32(pa[i].w);
                uint32_t* q = Bs + buf * BS_TILE + (idx >> 5) * BS_STRIDE + (idx & 31) * 4;
                q[0] = f2tf32(pb[i].x); q[1] = f2tf32(pb[i].y);
                q[2] = f2tf32(pb[i].z); q[3] = f2tf32(pb[i].w);
            }
            __syncthreads();
        }
    }

    #pragma unroll
    for (int nt = 0; nt < 8; nt++) {
        const int cc = col0 + wn + nt * 8 + 2 * tig;
        const float b0 = bias ? bias[cc]     : 0.f;
        const float b1 = bias ? bias[cc + 1] : 0.f;
        #pragma unroll
        for (int mt = 0; mt < 4; mt++) {
            const int r = row0 + wm + mt * 16 + gid;
            float2 v0 = make_float2(c[mt][nt][0] + b0, c[mt][nt][1] + b1);
            float2 v1 = make_float2(c[mt][nt][2] + b0, c[mt][nt][3] + b1);
            *(float2*)&C[(size_t)r * N + cc]       = v0;
            *(float2*)&C[(size_t)(r + 8) * N + cc] = v1;
        }
    }
}

// ---------------------------------------------------------------------------
// FA2-style tensor-core causal flash attention. 256 threads = 8 warps.
// Q tile 256 rows; warp tile 32x64 (2 m-subtiles). Softmax warp-private.
// KEY: PV mma consumes the S/P accumulator fragments DIRECTLY as A operands
// (c-layout {c0,c2,c1,c3} == a-layout over j-pairs (2tig,2tig+1)) with V
// stored transposed in identity j-order -> zero shuffles, zero P smem.
// FSTR=72 makes all uint2 fragment reads bank-conflict-free. exp2 softmax
// with log2(e) folded into the Q scale.
// ---------------------------------------------------------------------------
#define FSTR 72
#define QROWS 256
#define FLASH_SMEM ((QROWS + 64 + 64) * FSTR * 4)  // 110592 B

__global__ __launch_bounds__(256) void flash_mma(const float* __restrict__ qkv,
                                                 float* __restrict__ out)
{
    extern __shared__ uint32_t smu[];
    uint32_t* Qt = smu;                  // [256 r][FSTR] tf32, k-pair-permuted
    uint32_t* Kt = Qt + QROWS * FSTR;    // [64 j][FSTR]  tf32, k-pair-permuted
    uint32_t* Vt = Kt + 64 * FSTR;       // [64 d][FSTR]  tf32, V^T identity j

    const int tid  = threadIdx.x;
    const int lane = tid & 31;
    const int wid  = tid >> 5;          // 0..7
    const int wm   = wid * 32;          // warp's 32 query rows
    const int gid  = lane >> 2;
    const int tig  = lane & 3;
    const int qt   = gridDim.x - 1 - blockIdx.x;  // heavy blocks first
    const int h    = blockIdx.y;
    const int b    = blockIdx.z;

    // --- load Q tile (1 thread/row), scale by SCALE*log2e, k-pair permute ---
    {
        const float* qrow = qkv + ((size_t)(b * SEQ + qt * QROWS + tid)) * QKV_N + h * HEAD_DIM;
        #pragma unroll
        for (int it = 0; it < 16; it++) {
            const int d4 = it * 4;
            float4 v = *(const float4*)(qrow + d4);
            uint32_t* p = Qt + tid * FSTR + (d4 & ~7) + ((d4 >> 2) & 1);
            p[0] = f2tf32(v.x * SCALE_LOG2E);
            p[2] = f2tf32(v.y * SCALE_LOG2E);
            p[4] = f2tf32(v.z * SCALE_LOG2E);
            p[6] = f2tf32(v.w * SCALE_LOG2E);
        }
    }

    // --- K/V register prefetch (4 threads/row, 16 els each) ---
    const int r63 = tid & 63;
    const int cg0 = tid >> 6;           // 0..3
    float4 ka[4], va[4];
    {
        const float* kb = qkv + ((size_t)(b * SEQ + r63)) * QKV_N + D_MODEL + h * HEAD_DIM;
        #pragma unroll
        for (int it = 0; it < 4; it++) {
            const int d4 = cg0 * 16 + it * 4;
            ka[it] = *(const float4*)(kb + d4);
            va[it] = *(const float4*)(kb + D_MODEL + d4);
        }
    }

    float co[2][8][4] = {};    // O fragments: 2 m-subtiles x 8 d-tiles
    float m[4], l[4];          // [s*2+g]: subtile s, row-group g (gid / gid+8)
    #pragma unroll
    for (int i = 0; i < 4; i++) { m[i] = -1e30f; l[i] = 0.f; }

    const int rbase = qt * QROWS + wm + gid;
    const int ktmax = 4 * qt + 3;

    for (int kt = 0; kt <= ktmax; kt++) {
        __syncthreads();  // previous tile's consumers done with Kt/Vt

        // store prefetched K (k-pair permuted) and V (transposed, identity j)
        #pragma unroll
        for (int it = 0; it < 4; it++) {
            const int d4 = cg0 * 16 + it * 4;
            uint32_t* p = Kt + r63 * FSTR + (d4 & ~7) + ((d4 >> 2) & 1);
            p[0] = f2tf32(ka[it].x);
            p[2] = f2tf32(ka[it].y);
            p[4] = f2tf32(ka[it].z);
            p[6] = f2tf32(ka[it].w);
            Vt[(d4 + 0) * FSTR + r63] = f2tf32(va[it].x);
            Vt[(d4 + 1) * FSTR + r63] = f2tf32(va[it].y);
            Vt[(d4 + 2) * FSTR + r63] = f2tf32(va[it].z);
            Vt[(d4 + 3) * FSTR + r63] = f2tf32(va[it].w);
        }
        __syncthreads();

        // prefetch next K/V tile into registers
        if (kt < ktmax) {
            const float* kb = qkv + ((size_t)(b * SEQ + (kt + 1) * 64 + r63)) * QKV_N
                              + D_MODEL + h * HEAD_DIM;
            #pragma unroll
            for (int it = 0; it < 4; it++) {
                const int d4 = cg0 * 16 + it * 4;
                ka[it] = *(const float4*)(kb + d4);
                va[it] = *(const float4*)(kb + D_MODEL + d4);
            }
        }

        // --- S = Q K^T (log2-domain scores) ---
        float cs[2][8][4] = {};
        #pragma unroll
        for (int ks = 0; ks < 8; ks++) {
            uint32_t af[2][4];
            #pragma unroll
            for (int s = 0; s < 2; s++) {
                const uint2 qlo = *(const uint2*)&Qt[(wm + s * 16 + gid) * FSTR + ks * 8 + 2 * tig];
                const uint2 qhi = *(const uint2*)&Qt[(wm + s * 16 + gid + 8) * FSTR + ks * 8 + 2 * tig];
                af[s][0] = qlo.x; af[s][1] = qhi.x; af[s][2] = qlo.y; af[s][3] = qhi.y;
            }
            #pragma unroll
            for (int nt = 0; nt < 8; nt++) {
                const uint2 kb2 = *(const uint2*)&Kt[(nt * 8 + gid) * FSTR + ks * 8 + 2 * tig];
                uint32_t bf[2] = { kb2.x, kb2.y };
                mma_tf32(cs[0][nt], af[0], bf);
                mma_tf32(cs[1][nt], af[1], bf);
            }
        }

        // --- causal mask (diagonal-band tiles only) ---
        if (kt >= 4 * qt) {
            #pragma unroll
            for (int s = 0; s < 2; s++) {
                const int r0 = rbase + s * 16;
                const int r1 = r0 + 8;
                #pragma unroll
                for (int nt = 0; nt < 8; nt++) {
                    const int j0 = kt * 64 + nt * 8 + 2 * tig;
                    if (j0     > r0) cs[s][nt][0] = -1e30f;
                    if (j0 + 1 > r0) cs[s][nt][1] = -1e30f;
                    if (j0     > r1) cs[s][nt][2] = -1e30f;
                    if (j0 + 1 > r1) cs[s][nt][3] = -1e30f;
                }
            }
        }

        // --- warp-private online softmax (exp2 domain, quad reductions) ---
        #pragma unroll
        for (int s = 0; s < 2; s++) {
            float tm0 = -1e30f, tm1 = -1e30f;
            #pragma unroll
            for (int nt = 0; nt < 8; nt++) {
                tm0 = fmaxf(tm0, fmaxf(cs[s][nt][0], cs[s][nt][1]));
                tm1 = fmaxf(tm1, fmaxf(cs[s][nt][2], cs[s][nt][3]));
            }
            tm0 = fmaxf(tm0, __shfl_xor_sync(0xFFFFFFFFu, tm0, 1));
            tm0 = fmaxf(tm0, __shfl_xor_sync(0xFFFFFFFFu, tm0, 2));
            tm1 = fmaxf(tm1, __shfl_xor_sync(0xFFFFFFFFu, tm1, 1));
            tm1 = fmaxf(tm1, __shfl_xor_sync(0xFFFFFFFFu, tm1, 2));

            const float mn0 = fmaxf(m[s * 2 + 0], tm0);
            const float mn1 = fmaxf(m[s * 2 + 1], tm1);
            const float al0 = fexp2(m[s * 2 + 0] - mn0);
            const float al1 = fexp2(m[s * 2 + 1] - mn1);
            m[s * 2 + 0] = mn0; m[s * 2 + 1] = mn1;

            float rs0 = 0.f, rs1 = 0.f;
            #pragma unroll
            for (int nt = 0; nt < 8; nt++) {
                cs[s][nt][0] = fexp2(cs[s][nt][0] - mn0);
                cs[s][nt][1] = fexp2(cs[s][nt][1] - mn0);
                cs[s][nt][2] = fexp2(cs[s][nt][2] - mn1);
                cs[s][nt][3] = fexp2(cs[s][nt][3] - mn1);
                rs0 += cs[s][nt][0] + cs[s][nt][1];
                rs1 += cs[s][nt][2] + cs[s][nt][3];
            }
            rs0 += __shfl_xor_sync(0xFFFFFFFFu, rs0, 1);
            rs0 += __shfl_xor_sync(0xFFFFFFFFu, rs0, 2);
            rs1 += __shfl_xor_sync(0xFFFFFFFFu, rs1, 1);
            rs1 += __shfl_xor_sync(0xFFFFFFFFu, rs1, 2);
            l[s * 2 + 0] = l[s * 2 + 0] * al0 + rs0;
            l[s * 2 + 1] = l[s * 2 + 1] * al1 + rs1;

            #pragma unroll
            for (int nt = 0; nt < 8; nt++) {
                co[s][nt][0] *= al0; co[s][nt][1] *= al0;
                co[s][nt][2] *= al1; co[s][nt][3] *= al1;
            }
        }

        // --- O += P V: P accumulators reused directly as A fragments ---
        // a-layout = {P[gid][2tig], P[gid+8][2tig], P[gid][2tig+1], P[gid+8][2tig+1]}
        //          = {c0, c2, c1, c3}; V^T uint2 supplies rows (2tig, 2tig+1).
        #pragma unroll
        for (int ks = 0; ks < 8; ks++) {
            uint32_t pa[2][4];
            #pragma unroll
            for (int s = 0; s < 2; s++) {
                pa[s][0] = f2tf32(cs[s][ks][0]);
                pa[s][1] = f2tf32(cs[s][ks][2]);
                pa[s][2] = f2tf32(cs[s][ks][1]);
                pa[s][3] = f2tf32(cs[s][ks][3]);
            }
            #pragma unroll
            for (int nt = 0; nt < 8; nt++) {
                const uint2 vb2 = *(const uint2*)&Vt[(nt * 8 + gid) * FSTR + ks * 8 + 2 * tig];
                uint32_t bf[2] = { vb2.x, vb2.y };
                mma_tf32(co[0][nt], pa[0], bf);
                mma_tf32(co[1][nt], pa[1], bf);
            }
        }
    }

    // --- epilogue ---
    float* ob = out + ((size_t)(b * SEQ + qt * QROWS)) * D_MODEL + h * HEAD_DIM;
    #pragma unroll
    for (int s = 0; s < 2; s++) {
        const float inv0 = 1.f / l[s * 2 + 0];
        const float inv1 = 1.f / l[s * 2 + 1];
        #pragma unroll
        for (int nt = 0; nt < 8; nt++) {
            const int cc = nt * 8 + 2 * tig;
            float2 v0 = make_float2(co[s][nt][0] * inv0, co[s][nt][1] * inv0);
            float2 v1 = make_float2(co[s][nt][2] * inv1, co[s][nt][3] * inv1);
            *(float2*)&ob[(size_t)(wm + s * 16 + gid) * D_MODEL + cc]     = v0;
            *(float2*)&ob[(size_t)(wm + s * 16 + gid + 8) * D_MODEL + cc] = v1;
        }
    }
}

// ---------------------------------------------------------------------------
// Launch: tf32 QKV GEMM -> tf32 flash attention -> tf32 out projection (+bias)
// Inputs: x, attn_mask (ignored; causal known), W_qkv, W_proj, b_proj
// ---------------------------------------------------------------------------
extern "C" void kernel_launch(void* const* d_in, const int* in_sizes, int n_in,
                              void* d_out, int out_size)
{
    (void)in_sizes; (void)n_in; (void)out_size;
    const float* x      = (const float*)d_in[0];
    const float* W_qkv  = (const float*)d_in[2];
    const float* W_proj = (const float*)d_in[3];
    const float* b_proj = (const float*)d_in[4];
    float* out = (float*)d_out;

    float *qkv, *attn;
    cudaGetSymbolAddress((void**)&qkv,  g_qkv);
    cudaGetSymbolAddress((void**)&attn, g_attn);

    cudaFuncSetAttribute(gemm_tf32, cudaFuncAttributeMaxDynamicSharedMemorySize, GEMM_SMEM);
    cudaFuncSetAttribute(flash_mma, cudaFuncAttributeMaxDynamicSharedMemorySize, FLASH_SMEM);

    // 1) QKV projection: [4096,768] @ [768,2304]  (tf32 tensor cores)
    gemm_tf32<<<dim3(QKV_N / 128, M_TOK / 128), 128, GEMM_SMEM>>>(x, W_qkv, nullptr, qkv,
                                                                  M_TOK, QKV_N, D_MODEL);

    // 2) causal flash attention per (q-tile, head, batch)  (tf32 tensor cores)
    flash_mma<<<dim3(SEQ / QROWS, N_HEADS, BATCH), 256, FLASH_SMEM>>>(qkv, attn);

    // 3) output projection + bias: [4096,768] @ [768,768]  (tf32 tensor cores)
    gemm_tf32<<<dim3(D_MODEL / 128, M_TOK / 128), 128, GEMM_SMEM>>>(attn, W_proj, b_proj, out,
                                                                    M_TOK, D_MODEL, D_MODEL);
}